// round 1
// baseline (speedup 1.0000x reference)
#include <cuda_runtime.h>

// Problem constants (fixed by the reference)
#define NB   32        // batch
#define ND   1024      // input dim
#define NH   1024      // hidden dim
#define BETA 0.9f

// Derived closed forms:
//   u_new = BETA*u + x@w + b        [B,H]
//   out   = tanh(u_new)             [B,H]
//   E_w'  = BETA*E_w + x[b,d]       [1,B,D,H]
//   E_b'  = BETA*E_b + 1            [1,B,H]
//
// Output buffer layout (flattened concat in reference return order):
//   [0,                BH)              out
//   [BH,               2BH)             u_new
//   [2BH,              2BH + B*D*H)     E_w'
//   [2BH + B*D*H,      3BH + B*D*H)     E_b'

#define NB_GEMM 64     // blocks doing GEMM+epilogue; rest stream E_w
#define TPB     256

__global__ __launch_bounds__(TPB, 8)
void diag_rtrl_fused(const float* __restrict__ x,
                     const float* __restrict__ w,
                     const float* __restrict__ bias,
                     const float* __restrict__ u,
                     const float* __restrict__ Ew,
                     const float* __restrict__ Eb,
                     float* __restrict__ out)
{
    const int BH = NB * NH;
    float* o_out = out;                       // [B,H]
    float* o_u   = out + BH;                  // [B,H]
    float* o_Ew  = out + 2 * BH;              // [B,D,H]
    float* o_Eb  = out + 2 * BH + NB * ND * NH; // [B,H]

    if (blockIdx.x < NB_GEMM) {
        // ---- GEMM + u_new + out + E_b blocks ----
        // 16 b-groups (2 rows each) x 4 h-tiles (256 cols each) = 64 blocks
        __shared__ float xs[2][ND];           // 8 KB
        const int bg = blockIdx.x >> 2;       // 0..15
        const int ht = blockIdx.x & 3;        // 0..3
        const int b0 = bg * 2;
        const int tid = threadIdx.x;

        #pragma unroll
        for (int j = 0; j < 2; j++)
            for (int d = tid; d < ND; d += TPB)
                xs[j][d] = x[(b0 + j) * ND + d];
        __syncthreads();

        const int h = ht * TPB + tid;         // coalesced over w columns
        float acc0 = 0.f, acc1 = 0.f;
        #pragma unroll 8
        for (int d = 0; d < ND; d++) {
            float wv = w[d * NH + h];
            acc0 = fmaf(xs[0][d], wv, acc0);
            acc1 = fmaf(xs[1][d], wv, acc1);
        }
        const float bv = bias[h];

        {
            const int i0 = (b0 + 0) * NH + h;
            float un = fmaf(BETA, u[i0], acc0 + bv);
            o_u[i0]   = un;
            o_out[i0] = tanhf(un);
            o_Eb[i0]  = fmaf(BETA, Eb[i0], 1.0f);
        }
        {
            const int i1 = (b0 + 1) * NH + h;
            float un = fmaf(BETA, u[i1], acc1 + bv);
            o_u[i1]   = un;
            o_out[i1] = tanhf(un);
            o_Eb[i1]  = fmaf(BETA, Eb[i1], 1.0f);
        }
    } else {
        // ---- E_w streaming blocks: E_w' = BETA*E_w + x[b,d], float4 ----
        const long long nvec = (long long)NB * ND * NH / 4;  // 8388608
        const long long nblk = (long long)gridDim.x - NB_GEMM;
        const long long stride = nblk * TPB;
        long long i = (long long)(blockIdx.x - NB_GEMM) * TPB + threadIdx.x;

        const float4* Ew4 = (const float4*)Ew;
        float4*       O4  = (float4*)o_Ew;

        for (; i < nvec; i += stride) {
            // H/4 = 256 float4 per (b,d); flat (b*D+d) == flat index into x
            const int bd = (int)(i >> 8);
            const float xv = __ldg(&x[bd]);
            float4 e = __ldcs(&Ew4[i]);       // streaming read: no L2 reuse
            float4 r;
            r.x = fmaf(BETA, e.x, xv);
            r.y = fmaf(BETA, e.y, xv);
            r.z = fmaf(BETA, e.z, xv);
            r.w = fmaf(BETA, e.w, xv);
            __stcs(&O4[i], r);                // streaming write
        }
    }
}

extern "C" void kernel_launch(void* const* d_in, const int* in_sizes, int n_in,
                              void* d_out, int out_size)
{
    const float* x   = (const float*)d_in[0];  // [32,1024]
    const float* w   = (const float*)d_in[1];  // [1024,1024]
    const float* b   = (const float*)d_in[2];  // [1024]
    const float* u   = (const float*)d_in[3];  // [32,1024]
    const float* Ew  = (const float*)d_in[4];  // [1,32,1024,1024]
    const float* Eb  = (const float*)d_in[5];  // [1,32,1024]
    float* out = (float*)d_out;

    // One full wave: 148 SMs x 8 blocks of 256 threads (sm_100a has 148 SMs).
    const int grid = 148 * 8;                  // 64 GEMM blocks + 1120 E_w blocks
    diag_rtrl_fused<<<grid, TPB>>>(x, w, b, u, Ew, Eb, out);
}